// round 4
// baseline (speedup 1.0000x reference)
#include <cuda_runtime.h>
#include <cstdint>

#define N_NODES 50000
#define N_EDGES 640000
#define D 128
#define N_RELS 16
#define N_NT 8
#define TILE 128

#define EG (N_EDGES / TILE + N_RELS)            /* 5016 tiles max for edge gemm */
#define NG ((N_NODES + TILE - 1) / TILE + N_NT) /* 399 tiles max for node gemm */
#define E_PAD (EG * TILE)
#define N_PAD (NG * TILE)

#define SROW 132                        /* padded smem row stride (floats) */
#define EDGE_SMEM (3 * 128 * SROW * 4)  /* sB + sA0 + sA1 = 202752 B */
#define NODE_SMEM (2 * 128 * SROW * 4)  /* 135168 B */
#define WT_SMEM (128 * 132 * 4)
#define EDGE_GRID 148

/* ------------------------------ scratch ------------------------------ */
__device__ int   g_counts[N_NODES * N_RELS];
__device__ int   g_rel_cnt[N_RELS];
__device__ int   g_rel_cur[N_RELS];
__device__ int   g_nt_cnt[N_NT];
__device__ int   g_nt_cur[N_NT];
__device__ int   g_eperm[E_PAD];
__device__ int   g_nperm[N_PAD];
__device__ float g_agg[N_NODES * D];
__device__ int   g_ntiles[2];
__device__ float g_WT[N_RELS * D * D];   /* W_edge^T: [r][f][d], tf32-rounded */
__device__ float g_WnT[N_NT * D * D];    /* W_node^T */
__device__ float g_featsR[N_NODES * D];  /* feats, tf32-rna-rounded */

/* ------------------------------ helpers ------------------------------ */
__device__ __forceinline__ uint32_t tf32r(float x) {
    uint32_t r;
    asm("cvt.rna.tf32.f32 %0, %1;" : "=r"(r) : "f"(x));
    return r;
}
__device__ __forceinline__ uint32_t smem_u32(const void* p) {
    uint32_t a;
    asm("{ .reg .u64 t; cvta.to.shared.u64 t, %1; cvt.u32.u64 %0, t; }" : "=r"(a) : "l"(p));
    return a;
}
__device__ __forceinline__ void cpa16(uint32_t dstS, const void* src) {
    asm volatile("cp.async.ca.shared.global [%0], [%1], 16;" :: "r"(dstS), "l"(src));
}
__device__ __forceinline__ void mma8(float* c, const uint32_t* a, const uint32_t* b) {
    asm volatile(
        "mma.sync.aligned.m16n8k8.row.col.f32.tf32.tf32.f32 "
        "{%0,%1,%2,%3}, {%4,%5,%6,%7}, {%8,%9}, {%0,%1,%2,%3};"
        : "+f"(c[0]), "+f"(c[1]), "+f"(c[2]), "+f"(c[3])
        : "r"(a[0]), "r"(a[1]), "r"(a[2]), "r"(a[3]), "r"(b[0]), "r"(b[1]));
}
__device__ __forceinline__ void red4(float* p, float x, float y, float z, float w) {
    asm volatile("red.global.add.v4.f32 [%0], {%1,%2,%3,%4};"
                 :: "l"(p), "f"(x), "f"(y), "f"(z), "f"(w) : "memory");
}

/* ------------------------------ setup kernels ------------------------------ */
__global__ void k_zero(const float* __restrict__ feats) {
    int i = blockIdx.x * blockDim.x + threadIdx.x;
    int stride = gridDim.x * blockDim.x;
    for (int j = i; j < N_NODES * D; j += stride) {
        g_agg[j] = 0.0f;
        g_featsR[j] = __uint_as_float(tf32r(feats[j]));
    }
    for (int j = i; j < N_NODES * N_RELS; j += stride) g_counts[j] = 0;
    for (int j = i; j < E_PAD; j += stride) g_eperm[j] = -1;
    for (int j = i; j < N_PAD; j += stride) g_nperm[j] = -1;
    if (i < N_RELS) g_rel_cnt[i] = 0;
    if (i < N_NT) g_nt_cnt[i] = 0;
}

__global__ void k_hist(const int* __restrict__ dst, const int* __restrict__ etypes,
                       const int* __restrict__ ntypes) {
    __shared__ int sh[N_RELS + N_NT];
    int tid = threadIdx.x;
    if (tid < N_RELS + N_NT) sh[tid] = 0;
    __syncthreads();
    int i = blockIdx.x * blockDim.x + tid;
    int stride = gridDim.x * blockDim.x;
    for (int e = i; e < N_EDGES; e += stride) {
        int t = etypes[e];
        atomicAdd(&sh[t], 1);
        atomicAdd(&g_counts[dst[e] * N_RELS + t], 1);
    }
    for (int n = i; n < N_NODES; n += stride) atomicAdd(&sh[N_RELS + ntypes[n]], 1);
    __syncthreads();
    if (tid < N_RELS) atomicAdd(&g_rel_cnt[tid], sh[tid]);
    else if (tid < N_RELS + N_NT) atomicAdd(&g_nt_cnt[tid - N_RELS], sh[tid]);
}

__global__ void k_scan() {
    int off = 0;
    for (int t = 0; t < N_RELS; t++) {
        g_rel_cur[t] = off;
        off += ((g_rel_cnt[t] + TILE - 1) / TILE) * TILE;
    }
    g_ntiles[0] = off / TILE;
    off = 0;
    for (int t = 0; t < N_NT; t++) {
        g_nt_cur[t] = off;
        off += ((g_nt_cnt[t] + TILE - 1) / TILE) * TILE;
    }
    g_ntiles[1] = off / TILE;
}

__global__ void k_scatter(const int* __restrict__ etypes, const int* __restrict__ ntypes) {
    __shared__ int s_cnt[N_RELS], s_base[N_RELS];
    const int CH = 2048;
    int tid = threadIdx.x;

    int nch = (N_EDGES + CH - 1) / CH;
    for (int ch = blockIdx.x; ch < nch; ch += gridDim.x) {
        int lo = ch * CH, hi = min(lo + CH, N_EDGES);
        if (tid < N_RELS) s_cnt[tid] = 0;
        __syncthreads();
        for (int e = lo + tid; e < hi; e += blockDim.x) atomicAdd(&s_cnt[etypes[e]], 1);
        __syncthreads();
        if (tid < N_RELS) {
            s_base[tid] = atomicAdd(&g_rel_cur[tid], s_cnt[tid]);
            s_cnt[tid] = 0;
        }
        __syncthreads();
        for (int e = lo + tid; e < hi; e += blockDim.x) {
            int t = etypes[e];
            g_eperm[s_base[t] + atomicAdd(&s_cnt[t], 1)] = e;
        }
        __syncthreads();
    }

    nch = (N_NODES + CH - 1) / CH;
    for (int ch = blockIdx.x; ch < nch; ch += gridDim.x) {
        int lo = ch * CH, hi = min(lo + CH, N_NODES);
        if (tid < N_NT) s_cnt[tid] = 0;
        __syncthreads();
        for (int n = lo + tid; n < hi; n += blockDim.x) atomicAdd(&s_cnt[ntypes[n]], 1);
        __syncthreads();
        if (tid < N_NT) {
            s_base[tid] = atomicAdd(&g_nt_cur[tid], s_cnt[tid]);
            s_cnt[tid] = 0;
        }
        __syncthreads();
        for (int n = lo + tid; n < hi; n += blockDim.x) {
            int t = ntypes[n];
            g_nperm[s_base[t] + atomicAdd(&s_cnt[t], 1)] = n;
        }
        __syncthreads();
    }
}

/* Transpose + tf32-round weights: g_WT[m][f*128+d] = rna_tf32(W[m][d*128+f]) */
__global__ void k_wt(const float* __restrict__ We, const float* __restrict__ Wn) {
    extern __shared__ float sT[]; /* [128][132] */
    int m = blockIdx.x;
    const float* Wsrc = (m < N_RELS) ? We + (size_t)m * D * D : Wn + (size_t)(m - N_RELS) * D * D;
    float* Wdst = (m < N_RELS) ? g_WT + (size_t)m * D * D : g_WnT + (size_t)(m - N_RELS) * D * D;
    int tid = threadIdx.x;
#pragma unroll
    for (int i = 0; i < 16; i++) {
        int lin = tid + 256 * i;
        int d = lin >> 5, fq = lin & 31;
        float4 v = *(const float4*)(Wsrc + d * D + fq * 4);
        sT[d * 132 + fq * 4 + 0] = __uint_as_float(tf32r(v.x));
        sT[d * 132 + fq * 4 + 1] = __uint_as_float(tf32r(v.y));
        sT[d * 132 + fq * 4 + 2] = __uint_as_float(tf32r(v.z));
        sT[d * 132 + fq * 4 + 3] = __uint_as_float(tf32r(v.w));
    }
    __syncthreads();
#pragma unroll
    for (int i = 0; i < 16; i++) {
        int lin = tid + 256 * i;
        int f = lin >> 5, dq = lin & 31;
        float4 v;
        v.x = sT[(dq * 4 + 0) * 132 + f];
        v.y = sT[(dq * 4 + 1) * 132 + f];
        v.z = sT[(dq * 4 + 2) * 132 + f];
        v.w = sT[(dq * 4 + 3) * 132 + f];
        *(float4*)(Wdst + f * D + dq * 4) = v;
    }
}

/* ------------------------------ persistent edge GEMM ------------------------------ */
/* 148 persistent CTAs, contiguous tile chunks. B cached in smem across tiles of the
 * same relation; A double-buffered via cp.async from pre-rounded g_featsR. */
__global__ __launch_bounds__(256, 1) void k_edge_p(
    const float* __restrict__ b_edge, const int* __restrict__ src,
    const int* __restrict__ dst, const int* __restrict__ etypes) {
    extern __shared__ float smf[];
    float* sB = smf;                       /* [128][SROW] */
    float* sAbuf[2] = {smf + 128 * SROW, smf + 2 * 128 * SROW};

    __shared__ int sDst[2][TILE];
    __shared__ float sInv[2][TILE];
    __shared__ int sRel[2];
    __shared__ float sBias[TILE];

    const int ntiles = g_ntiles[0];
    const int per = (ntiles + EDGE_GRID - 1) / EDGE_GRID;
    const int c0 = blockIdx.x * per;
    const int c1 = min(c0 + per, ntiles);
    if (c0 >= c1) return;

    const int tid = threadIdx.x, wid = tid >> 5, lane = tid & 31;
    const int wm = wid & 1, wn = wid >> 1;
    const int r_base = wm * 64, c_base = wn * 32;
    const int lq = lane >> 2, lr = lane & 3;

    /* ---- prefetch tile t into buffer t&1 ---- */
    auto prefetch = [&](int t) {
        int b = t & 1;
        int r = tid >> 1, h = tid & 1;
        int e = g_eperm[t * TILE + r];
        int s = (e >= 0) ? src[e] : 0;
        const float* gp = g_featsR + (size_t)s * D + h * 64;
        uint32_t sa = smem_u32(sAbuf[b] + r * SROW + h * 64);
#pragma unroll
        for (int c = 0; c < 16; c++) cpa16(sa + c * 16, gp + c * 4);
        asm volatile("cp.async.commit_group;" ::: "memory");
        if (h == 0) {
            int dn = -1;
            float inv = 0.0f;
            if (e >= 0) {
                dn = dst[e];
                int et = etypes[e];
                inv = 1.0f / (float)g_counts[dn * N_RELS + et];
                if (r == 0) sRel[b] = et;
            }
            sDst[b][r] = dn;
            sInv[b][r] = inv;
        }
    };

    prefetch(c0);
    int cur_rel = -1;

    for (int t = c0; t < c1; t++) {
        const int b = t & 1;
        if (t + 1 < c1) {
            prefetch(t + 1);
            asm volatile("cp.async.wait_group 1;" ::: "memory");
        } else {
            asm volatile("cp.async.wait_group 0;" ::: "memory");
        }
        __syncthreads();

        const int rel = sRel[b];
        if (rel != cur_rel) {
            cur_rel = rel;
            const float* Wr = g_WT + (size_t)rel * D * D;
#pragma unroll
            for (int i = 0; i < 16; i++) {
                int lin = tid + 256 * i;
                int f = lin >> 5, kq = lin & 31;
                *(float4*)(sB + f * SROW + kq * 4) = *(const float4*)(Wr + f * D + kq * 4);
            }
            if (tid < TILE) sBias[tid] = b_edge[rel * D + tid];
            __syncthreads();
        }

        /* mainloop */
        const uint32_t* sAu = (const uint32_t*)sAbuf[b];
        const uint32_t* sBu = (const uint32_t*)sB;
        float acc[4][4][4];
#pragma unroll
        for (int mt = 0; mt < 4; mt++)
#pragma unroll
            for (int nt = 0; nt < 4; nt++)
#pragma unroll
                for (int j = 0; j < 4; j++) acc[mt][nt][j] = 0.0f;

#pragma unroll 4
        for (int k0 = 0; k0 < 16; k0++) {
            const int kk = k0 * 8 + lr;
            uint32_t a[4][4], bb[4][2];
#pragma unroll
            for (int mt = 0; mt < 4; mt++) {
                int row = r_base + mt * 16 + lq;
                a[mt][0] = sAu[row * SROW + kk];
                a[mt][1] = sAu[(row + 8) * SROW + kk];
                a[mt][2] = sAu[row * SROW + kk + 4];
                a[mt][3] = sAu[(row + 8) * SROW + kk + 4];
            }
#pragma unroll
            for (int nt = 0; nt < 4; nt++) {
                int n = c_base + nt * 8 + lq;
                bb[nt][0] = sBu[n * SROW + kk];
                bb[nt][1] = sBu[n * SROW + kk + 4];
            }
#pragma unroll
            for (int mt = 0; mt < 4; mt++)
#pragma unroll
                for (int nt = 0; nt < 4; nt++) mma8(acc[mt][nt], a[mt], bb[nt]);
        }

        /* snapshot per-row meta to regs, then free the buffer for prefetch(t+2) */
        int dnr[4][2];
        float invr[4][2];
#pragma unroll
        for (int mt = 0; mt < 4; mt++)
#pragma unroll
            for (int h = 0; h < 2; h++) {
                int rr = r_base + mt * 16 + lq + h * 8;
                dnr[mt][h] = sDst[b][rr];
                invr[mt][h] = sInv[b][rr];
            }
        __syncthreads();

        /* epilogue: lane-pair shuffle -> red.v4 by even-lr lanes (half the L2 ops) */
#pragma unroll
        for (int mt = 0; mt < 4; mt++) {
#pragma unroll
            for (int h = 0; h < 2; h++) {
                int dn = dnr[mt][h];
                float inv = invr[mt][h];
#pragma unroll
                for (int nt = 0; nt < 4; nt++) {
                    int col = c_base + nt * 8 + lr * 2;
                    float x = (acc[mt][nt][h * 2 + 0] + sBias[col]) * inv;
                    float y = (acc[mt][nt][h * 2 + 1] + sBias[col + 1]) * inv;
                    float px = __shfl_xor_sync(0xFFFFFFFFu, x, 1);
                    float py = __shfl_xor_sync(0xFFFFFFFFu, y, 1);
                    if (dn >= 0 && (lr & 1) == 0)
                        red4(g_agg + (size_t)dn * D + col, x, y, px, py);
                }
            }
        }
    }
}

/* ------------------------------ mma.sync node GEMM + residual + relu ------------------------------ */
__global__ __launch_bounds__(256, 1) void k_node_mma(
    const float* __restrict__ b_node, const int* __restrict__ ntypes,
    float* __restrict__ out) {
    if ((int)blockIdx.x >= g_ntiles[1]) return;

    extern __shared__ float smf[];
    float* sA = smf;
    float* sB = smf + 128 * SROW;
    const uint32_t* sAu = (const uint32_t*)sA;
    const uint32_t* sBu = (const uint32_t*)sB;

    __shared__ int sNode[TILE];
    __shared__ float sBias[TILE];
    __shared__ int sNt;

    const int tid = threadIdx.x, wid = tid >> 5, lane = tid & 31;
    const int base = blockIdx.x * TILE;

    if (tid < TILE) {
        int n = g_nperm[base + tid];
        sNode[tid] = n;
        if (tid == 0) sNt = ntypes[n]; /* row 0 of a live tile is always valid */
    }
    __syncthreads();
    const int nt_ = sNt;
    if (tid < TILE) sBias[tid] = b_node[nt_ * D + tid];

    {
        int r = tid >> 1, half = tid & 1;
        int n = sNode[r];
        const float4* fp = (const float4*)(g_featsR + (size_t)(n >= 0 ? n : 0) * D) + half * 16;
        float* ap = sA + r * SROW + half * 64;
#pragma unroll
        for (int i = 0; i < 16; i++) *(float4*)(ap + i * 4) = fp[i];
    }
    {
        const float* Wr = g_WnT + (size_t)nt_ * D * D;
#pragma unroll
        for (int i = 0; i < 16; i++) {
            int lin = tid + 256 * i;
            int f = lin >> 5, kq = lin & 31;
            *(float4*)(sB + f * SROW + kq * 4) = *(const float4*)(Wr + f * D + kq * 4);
        }
    }
    __syncthreads();

    const int wm = wid & 1, wn = wid >> 1;
    const int r_base = wm * 64, c_base = wn * 32;
    const int lq = lane >> 2, lr = lane & 3;

    float acc[4][4][4];
#pragma unroll
    for (int mt = 0; mt < 4; mt++)
#pragma unroll
        for (int ntl = 0; ntl < 4; ntl++)
#pragma unroll
            for (int j = 0; j < 4; j++) acc[mt][ntl][j] = 0.0f;

#pragma unroll 4
    for (int k0 = 0; k0 < 16; k0++) {
        const int kk = k0 * 8 + lr;
        uint32_t a[4][4], b[4][2];
#pragma unroll
        for (int mt = 0; mt < 4; mt++) {
            int row = r_base + mt * 16 + lq;
            a[mt][0] = sAu[row * SROW + kk];
            a[mt][1] = sAu[(row + 8) * SROW + kk];
            a[mt][2] = sAu[row * SROW + kk + 4];
            a[mt][3] = sAu[(row + 8) * SROW + kk + 4];
        }
#pragma unroll
        for (int ntl = 0; ntl < 4; ntl++) {
            int n = c_base + ntl * 8 + lq;
            b[ntl][0] = sBu[n * SROW + kk];
            b[ntl][1] = sBu[n * SROW + kk + 4];
        }
#pragma unroll
        for (int mt = 0; mt < 4; mt++)
#pragma unroll
            for (int ntl = 0; ntl < 4; ntl++) mma8(acc[mt][ntl], a[mt], b[ntl]);
    }

    /* epilogue: relu(acc + bias + agg) -> out */
#pragma unroll
    for (int mt = 0; mt < 4; mt++) {
        int row0 = r_base + mt * 16 + lq;
#pragma unroll
        for (int h = 0; h < 2; h++) {
            int rr = row0 + h * 8;
            int n = sNode[rr];
            if (n < 0) continue;
            const float* ab = g_agg + (size_t)n * D;
            float* ob = out + (size_t)n * D;
#pragma unroll
            for (int ntl = 0; ntl < 4; ntl++) {
                int col = c_base + ntl * 8 + lr * 2;
                float2 ag = *(const float2*)(ab + col);
                float2 o;
                o.x = fmaxf(acc[mt][ntl][h * 2 + 0] + sBias[col] + ag.x, 0.0f);
                o.y = fmaxf(acc[mt][ntl][h * 2 + 1] + sBias[col + 1] + ag.y, 0.0f);
                *(float2*)(ob + col) = o;
            }
        }
    }
}

/* ------------------------------ launch ------------------------------ */
extern "C" void kernel_launch(void* const* d_in, const int* in_sizes, int n_in,
                              void* d_out, int out_size) {
    const float* feats  = (const float*)d_in[0];
    const float* W_edge = (const float*)d_in[1];
    const float* b_edge = (const float*)d_in[2];
    const float* W_node = (const float*)d_in[3];
    const float* b_node = (const float*)d_in[4];
    const int* src    = (const int*)d_in[5];
    const int* dst    = (const int*)d_in[6];
    const int* ntypes = (const int*)d_in[7];
    const int* etypes = (const int*)d_in[8];
    float* out = (float*)d_out;
    (void)in_sizes; (void)n_in; (void)out_size;

    cudaFuncSetAttribute(k_edge_p, cudaFuncAttributeMaxDynamicSharedMemorySize, EDGE_SMEM);
    cudaFuncSetAttribute(k_node_mma, cudaFuncAttributeMaxDynamicSharedMemorySize, NODE_SMEM);
    cudaFuncSetAttribute(k_wt, cudaFuncAttributeMaxDynamicSharedMemorySize, WT_SMEM);

    k_zero<<<1024, 256>>>(feats);
    k_hist<<<640, 256>>>(dst, etypes, ntypes);
    k_wt<<<N_RELS + N_NT, 256, WT_SMEM>>>(W_edge, W_node);
    k_scan<<<1, 1>>>();
    k_scatter<<<320, 256>>>(etypes, ntypes);
    k_edge_p<<<EDGE_GRID, 256, EDGE_SMEM>>>(b_edge, src, dst, etypes);
    k_node_mma<<<NG, 256, NODE_SMEM>>>(b_node, ntypes, out);
}